// round 1
// baseline (speedup 1.0000x reference)
#include <cuda_runtime.h>
#include <math.h>

#define Nn 4096
#define ADIM 512
#define NHEADS 8
#define HDIM 64
#define SCALE 0.125f

// Scratch: projected K/V (both layouts [N, 512], head h = cols h*64..h*64+63)
__device__ float g_K1P[Nn * ADIM];
__device__ float g_V1P[Nn * ADIM];
__device__ float g_K2P[Nn * ADIM];
__device__ float g_V2P[Nn * ADIM];
__device__ float g_O1[Nn * ADIM];
__device__ float g_O2[Nn * ADIM];

struct Ptrs {
    const float* p[16];
};

// ---------------------------------------------------------------------------
// Projection GEMM: C[4096,512] = A[4096,256] @ W[256,512] + bias
// BM=64 BN=64 BK=32, 256 threads (16x16), 4x4 micro-tile.
// blockIdx.z selects which of the 4 projections.
// ---------------------------------------------------------------------------
__global__ __launch_bounds__(256) void proj_kernel(Ptrs in) {
    const float *A, *W, *bias;
    float* C;
    switch (blockIdx.z) {
        case 0: A = in.p[0]; W = in.p[4];  bias = in.p[5];  C = g_K1P; break;
        case 1: A = in.p[1]; W = in.p[6];  bias = in.p[7];  C = g_V1P; break;
        case 2: A = in.p[2]; W = in.p[8];  bias = in.p[9];  C = g_K2P; break;
        default:A = in.p[3]; W = in.p[10]; bias = in.p[11]; C = g_V2P; break;
    }
    __shared__ float As[64][33];
    __shared__ float Ws[32][65];

    const int tid = threadIdx.x;
    const int tx = tid & 15, ty = tid >> 4;
    const int row0 = blockIdx.y * 64;
    const int col0 = blockIdx.x * 64;

    float acc[4][4];
#pragma unroll
    for (int i = 0; i < 4; i++)
#pragma unroll
        for (int j = 0; j < 4; j++) acc[i][j] = 0.0f;

    for (int k0 = 0; k0 < 256; k0 += 32) {
#pragma unroll
        for (int i = tid; i < 64 * 32; i += 256) {
            int r = i >> 5, c = i & 31;
            As[r][c] = A[(row0 + r) * 256 + k0 + c];
        }
#pragma unroll
        for (int i = tid; i < 32 * 64; i += 256) {
            int r = i >> 6, c = i & 63;
            Ws[r][c] = W[(k0 + r) * 512 + col0 + c];
        }
        __syncthreads();
#pragma unroll
        for (int k = 0; k < 32; k++) {
            float a[4], b[4];
#pragma unroll
            for (int i = 0; i < 4; i++) a[i] = As[ty * 4 + i][k];
#pragma unroll
            for (int j = 0; j < 4; j++) b[j] = Ws[k][tx * 4 + j];
#pragma unroll
            for (int i = 0; i < 4; i++)
#pragma unroll
                for (int j = 0; j < 4; j++) acc[i][j] = fmaf(a[i], b[j], acc[i][j]);
        }
        __syncthreads();
    }
#pragma unroll
    for (int j = 0; j < 4; j++) {
        float bb = bias[col0 + tx * 4 + j];
#pragma unroll
        for (int i = 0; i < 4; i++)
            C[(row0 + ty * 4 + i) * 512 + col0 + tx * 4 + j] = acc[i][j] + bb;
    }
}

// ---------------------------------------------------------------------------
// Flash attention (fp32, exact online softmax).
// grid = (64 row-blocks, 8 heads, 2 directions)
//   z=0: O2 = softmax_m(K1p K2p^T) V2p   (Q=K1P, K=K2P, V=V2P)
//   z=1: O1 = softmax_n(S)^T V1p         (Q=K2P, K=K1P, V=V1P)
// Br=64 rows, Bc=32 keys per tile, d=64. 256 threads (16x16).
// S micro-tile 4x2 per thread, O micro-tile 4x4.
// ---------------------------------------------------------------------------
__global__ __launch_bounds__(256) void flash_kernel() {
    const float *Q, *K, *V;
    float* O;
    if (blockIdx.z == 0) { Q = g_K1P; K = g_K2P; V = g_V2P; O = g_O2; }
    else                 { Q = g_K2P; K = g_K1P; V = g_V1P; O = g_O1; }

    __shared__ float Qs[64][65];
    __shared__ float Ks[32][65];
    __shared__ float Vs[32][65];
    __shared__ float Ps[64][33];

    const int tid = threadIdx.x;
    const int tx = tid & 15, ty = tid >> 4;
    const int row0 = blockIdx.x * 64;
    const int hc = blockIdx.y * 64;

    // load Q tile [64 x 64]
#pragma unroll
    for (int i = tid; i < 64 * 64; i += 256) {
        int r = i >> 6, c = i & 63;
        Qs[r][c] = Q[(row0 + r) * 512 + hc + c];
    }

    float m_i[4], l_i[4], Oa[4][4];
#pragma unroll
    for (int i = 0; i < 4; i++) {
        m_i[i] = -INFINITY;
        l_i[i] = 0.0f;
#pragma unroll
        for (int j = 0; j < 4; j++) Oa[i][j] = 0.0f;
    }

    for (int t = 0; t < Nn / 32; t++) {
        const int kr0 = t * 32;
        __syncthreads();  // previous PV done (and first iter: Qs stores done)
#pragma unroll
        for (int i = tid; i < 32 * 64; i += 256) {
            int r = i >> 6, c = i & 63;
            Ks[r][c] = K[(kr0 + r) * 512 + hc + c];
            Vs[r][c] = V[(kr0 + r) * 512 + hc + c];
        }
        __syncthreads();

        // S = Q K^T * SCALE   (rows ty*4+i, cols tx*2+j)
        float s[4][2];
#pragma unroll
        for (int i = 0; i < 4; i++) { s[i][0] = 0.0f; s[i][1] = 0.0f; }
#pragma unroll
        for (int k = 0; k < 64; k++) {
            float b0 = Ks[tx * 2 + 0][k];
            float b1 = Ks[tx * 2 + 1][k];
#pragma unroll
            for (int i = 0; i < 4; i++) {
                float a = Qs[ty * 4 + i][k];
                s[i][0] = fmaf(a, b0, s[i][0]);
                s[i][1] = fmaf(a, b1, s[i][1]);
            }
        }

        // online softmax stats per row (replicated across the 16 tx lanes)
#pragma unroll
        for (int i = 0; i < 4; i++) {
            float s0 = s[i][0] * SCALE;
            float s1 = s[i][1] * SCALE;
            float mt = fmaxf(s0, s1);
#pragma unroll
            for (int off = 8; off > 0; off >>= 1)
                mt = fmaxf(mt, __shfl_xor_sync(0xffffffffu, mt, off));
            float mnew = fmaxf(m_i[i], mt);
            float alpha = __expf(m_i[i] - mnew);
            float p0 = __expf(s0 - mnew);
            float p1 = __expf(s1 - mnew);
            float lt = p0 + p1;
#pragma unroll
            for (int off = 8; off > 0; off >>= 1)
                lt += __shfl_xor_sync(0xffffffffu, lt, off);
            l_i[i] = l_i[i] * alpha + lt;
            m_i[i] = mnew;
            Ps[ty * 4 + i][tx * 2 + 0] = p0;
            Ps[ty * 4 + i][tx * 2 + 1] = p1;
#pragma unroll
            for (int j = 0; j < 4; j++) Oa[i][j] *= alpha;
        }
        __syncthreads();

        // O += P @ V  (dims tx*4+j)
#pragma unroll
        for (int c = 0; c < 32; c++) {
            float v[4];
#pragma unroll
            for (int j = 0; j < 4; j++) v[j] = Vs[c][tx * 4 + j];
#pragma unroll
            for (int i = 0; i < 4; i++) {
                float pv = Ps[ty * 4 + i][c];
#pragma unroll
                for (int j = 0; j < 4; j++) Oa[i][j] = fmaf(pv, v[j], Oa[i][j]);
            }
        }
    }

#pragma unroll
    for (int i = 0; i < 4; i++) {
        float inv = 1.0f / l_i[i];
#pragma unroll
        for (int j = 0; j < 4; j++)
            O[(row0 + ty * 4 + i) * 512 + hc + tx * 4 + j] = Oa[i][j] * inv;
    }
}

// ---------------------------------------------------------------------------
// Output GEMM: out[4096,256] = O[4096,512] @ Wo[512,256] + bias
// blockIdx.z: 0 -> (g_O1, wo1) at offset 0, 1 -> (g_O2, wo2) at offset N*256
// ---------------------------------------------------------------------------
__global__ __launch_bounds__(256) void outproj_kernel(Ptrs in, float* out) {
    const float* A;
    const float* W;
    const float* bias;
    float* C;
    if (blockIdx.z == 0) { A = g_O1; W = in.p[12]; bias = in.p[13]; C = out; }
    else                 { A = g_O2; W = in.p[14]; bias = in.p[15]; C = out + Nn * 256; }

    __shared__ float As[64][33];
    __shared__ float Ws[32][65];

    const int tid = threadIdx.x;
    const int tx = tid & 15, ty = tid >> 4;
    const int row0 = blockIdx.y * 64;
    const int col0 = blockIdx.x * 64;

    float acc[4][4];
#pragma unroll
    for (int i = 0; i < 4; i++)
#pragma unroll
        for (int j = 0; j < 4; j++) acc[i][j] = 0.0f;

    for (int k0 = 0; k0 < 512; k0 += 32) {
#pragma unroll
        for (int i = tid; i < 64 * 32; i += 256) {
            int r = i >> 5, c = i & 31;
            As[r][c] = A[(row0 + r) * 512 + k0 + c];
        }
#pragma unroll
        for (int i = tid; i < 32 * 64; i += 256) {
            int r = i >> 6, c = i & 63;
            Ws[r][c] = W[(k0 + r) * 256 + col0 + c];
        }
        __syncthreads();
#pragma unroll
        for (int k = 0; k < 32; k++) {
            float a[4], b[4];
#pragma unroll
            for (int i = 0; i < 4; i++) a[i] = As[ty * 4 + i][k];
#pragma unroll
            for (int j = 0; j < 4; j++) b[j] = Ws[k][tx * 4 + j];
#pragma unroll
            for (int i = 0; i < 4; i++)
#pragma unroll
                for (int j = 0; j < 4; j++) acc[i][j] = fmaf(a[i], b[j], acc[i][j]);
        }
        __syncthreads();
    }
#pragma unroll
    for (int j = 0; j < 4; j++) {
        float bb = bias[col0 + tx * 4 + j];
#pragma unroll
        for (int i = 0; i < 4; i++)
            C[(row0 + ty * 4 + i) * 256 + col0 + tx * 4 + j] = acc[i][j] + bb;
    }
}

extern "C" void kernel_launch(void* const* d_in, const int* in_sizes, int n_in,
                              void* d_out, int out_size) {
    Ptrs ptrs;
    for (int i = 0; i < 16; i++) ptrs.p[i] = (const float*)d_in[i];
    float* out = (float*)d_out;

    // 1) four input projections: [4096,256]@[256,512]+b
    {
        dim3 grid(512 / 64, Nn / 64, 4);
        proj_kernel<<<grid, 256>>>(ptrs);
    }
    // 2) dual flash attention (both softmax directions)
    {
        dim3 grid(Nn / 64, NHEADS, 2);
        flash_kernel<<<grid, 256>>>();
    }
    // 3) two output projections: [4096,512]@[512,256]+b
    {
        dim3 grid(256 / 64, Nn / 64, 2);
        outproj_kernel<<<grid, 256>>>(ptrs, out);
    }
}

// round 2
// speedup vs baseline: 3.1376x; 3.1376x over previous
#include <cuda_runtime.h>
#include <math.h>
#include <stdint.h>

#define Nn 4096
#define ADIM 512
#define NHEADS 8
#define HDIM 64
#define SCALE 0.125f
#define FULLM 0xffffffffu

// Scratch: projected K/V ([N, 512], head h = cols h*64..h*64+63)
__device__ float g_K1P[Nn * ADIM];
__device__ float g_V1P[Nn * ADIM];
__device__ float g_K2P[Nn * ADIM];
__device__ float g_V2P[Nn * ADIM];
__device__ float g_O1[Nn * ADIM];
__device__ float g_O2[Nn * ADIM];

struct Ptrs {
    const float* p[16];
};

__device__ __forceinline__ uint32_t f2tf32(float x) {
    uint32_t r;
    asm("cvt.rna.tf32.f32 %0, %1;" : "=r"(r) : "f"(x));
    return r;
}

__device__ __forceinline__ void mma_tf32(float c[4],
                                         uint32_t a0, uint32_t a1, uint32_t a2, uint32_t a3,
                                         uint32_t b0, uint32_t b1) {
    asm volatile(
        "mma.sync.aligned.m16n8k8.row.col.f32.tf32.tf32.f32 "
        "{%0,%1,%2,%3}, {%4,%5,%6,%7}, {%8,%9}, {%0,%1,%2,%3};\n"
        : "+f"(c[0]), "+f"(c[1]), "+f"(c[2]), "+f"(c[3])
        : "r"(a0), "r"(a1), "r"(a2), "r"(a3), "r"(b0), "r"(b1));
}

// ---------------------------------------------------------------------------
// Projection GEMM: C[4096,512] = A[4096,256] @ W[256,512] + bias
// ---------------------------------------------------------------------------
__global__ __launch_bounds__(256) void proj_kernel(Ptrs in) {
    const float *A, *W, *bias;
    float* C;
    switch (blockIdx.z) {
        case 0: A = in.p[0]; W = in.p[4];  bias = in.p[5];  C = g_K1P; break;
        case 1: A = in.p[1]; W = in.p[6];  bias = in.p[7];  C = g_V1P; break;
        case 2: A = in.p[2]; W = in.p[8];  bias = in.p[9];  C = g_K2P; break;
        default:A = in.p[3]; W = in.p[10]; bias = in.p[11]; C = g_V2P; break;
    }
    __shared__ float As[64][33];
    __shared__ float Ws[32][65];

    const int tid = threadIdx.x;
    const int tx = tid & 15, ty = tid >> 4;
    const int row0 = blockIdx.y * 64;
    const int col0 = blockIdx.x * 64;

    float acc[4][4];
#pragma unroll
    for (int i = 0; i < 4; i++)
#pragma unroll
        for (int j = 0; j < 4; j++) acc[i][j] = 0.0f;

    for (int k0 = 0; k0 < 256; k0 += 32) {
#pragma unroll
        for (int i = tid; i < 64 * 32; i += 256) {
            int r = i >> 5, c = i & 31;
            As[r][c] = A[(row0 + r) * 256 + k0 + c];
        }
#pragma unroll
        for (int i = tid; i < 32 * 64; i += 256) {
            int r = i >> 6, c = i & 63;
            Ws[r][c] = W[(k0 + r) * 512 + col0 + c];
        }
        __syncthreads();
#pragma unroll
        for (int k = 0; k < 32; k++) {
            float a[4], b[4];
#pragma unroll
            for (int i = 0; i < 4; i++) a[i] = As[ty * 4 + i][k];
#pragma unroll
            for (int j = 0; j < 4; j++) b[j] = Ws[k][tx * 4 + j];
#pragma unroll
            for (int i = 0; i < 4; i++)
#pragma unroll
                for (int j = 0; j < 4; j++) acc[i][j] = fmaf(a[i], b[j], acc[i][j]);
        }
        __syncthreads();
    }
#pragma unroll
    for (int j = 0; j < 4; j++) {
        float bb = bias[col0 + tx * 4 + j];
#pragma unroll
        for (int i = 0; i < 4; i++)
            C[(row0 + ty * 4 + i) * 512 + col0 + tx * 4 + j] = acc[i][j] + bb;
    }
}

// ---------------------------------------------------------------------------
// Flash attention with tf32 tensor-core MMA.
// grid = (4096/128 = 32 row-blocks, 8 heads, 2 directions), 256 threads.
//   z=0: O2 = softmax_row(K1p K2p^T) V2p
//   z=1: O1 = softmax_row(K2p K1p^T) V1p   (transposed-softmax direction)
// BR=128 (8 warps x m16), BC=32 keys/tile, d=64.
// Q A-fragments in registers; K,V tiles in smem (pad 68 / 72: conflict-free);
// P stays in registers, PV A-fragments built via intra-quad shfl permutation.
// ---------------------------------------------------------------------------
__global__ __launch_bounds__(256, 2) void flash_mma_kernel() {
    const float *Q, *K, *V;
    float* O;
    if (blockIdx.z == 0) { Q = g_K1P; K = g_K2P; V = g_V2P; O = g_O2; }
    else                 { Q = g_K2P; K = g_K1P; V = g_V1P; O = g_O1; }

    __shared__ float Ks[32][68];  // [key][dim]
    __shared__ float Vs[32][72];  // [key][dim]

    const int tid = threadIdx.x;
    const int lane = tid & 31;
    const int wid = tid >> 5;
    const int q = lane & 3;        // threadID in group (col within k8 / col-pair in C)
    const int g = lane >> 2;       // groupID (row within m16 half / col in B n8)
    const int row0 = blockIdx.x * 128;
    const int hc = blockIdx.y * 64;
    const int rowA = wid * 16 + g;   // block-local row, rowB = rowA + 8

    // ---- Q A-fragments in registers: 8 k-steps covering d=64 ----
    uint32_t qa[8][4];
    {
        const float* Qa = Q + (row0 + rowA) * 512 + hc;
        const float* Qb = Qa + 8 * 512;
#pragma unroll
        for (int kk = 0; kk < 8; kk++) {
            qa[kk][0] = f2tf32(Qa[kk * 8 + q]);
            qa[kk][1] = f2tf32(Qb[kk * 8 + q]);
            qa[kk][2] = f2tf32(Qa[kk * 8 + q + 4]);
            qa[kk][3] = f2tf32(Qb[kk * 8 + q + 4]);
        }
    }

    float o[8][4];
#pragma unroll
    for (int nt = 0; nt < 8; nt++)
#pragma unroll
        for (int j = 0; j < 4; j++) o[nt][j] = 0.0f;
    float mA = -INFINITY, mB = -INFINITY, lA = 0.0f, lB = 0.0f;

    for (int t = 0; t < Nn / 32; t++) {
        __syncthreads();
        // ---- fill K,V tile (tf32-converted), float4 loads/stores ----
#pragma unroll
        for (int it = 0; it < 2; it++) {
            int j = tid + it * 256;       // 0..511
            int r = j >> 4, c4 = j & 15;
            const float4 kv = *(const float4*)&K[(t * 32 + r) * 512 + hc + c4 * 4];
            const float4 vv = *(const float4*)&V[(t * 32 + r) * 512 + hc + c4 * 4];
            float4 ko, vo;
            ko.x = __uint_as_float(f2tf32(kv.x)); ko.y = __uint_as_float(f2tf32(kv.y));
            ko.z = __uint_as_float(f2tf32(kv.z)); ko.w = __uint_as_float(f2tf32(kv.w));
            vo.x = __uint_as_float(f2tf32(vv.x)); vo.y = __uint_as_float(f2tf32(vv.y));
            vo.z = __uint_as_float(f2tf32(vv.z)); vo.w = __uint_as_float(f2tf32(vv.w));
            *(float4*)&Ks[r][c4 * 4] = ko;
            *(float4*)&Vs[r][c4 * 4] = vo;
        }
        __syncthreads();

        // ---- S = Q K^T (warp tile 16 x 32, 4 n-tiles) ----
        float s[4][4];
#pragma unroll
        for (int nt = 0; nt < 4; nt++)
#pragma unroll
            for (int j = 0; j < 4; j++) s[nt][j] = 0.0f;
#pragma unroll
        for (int kk = 0; kk < 8; kk++) {
#pragma unroll
            for (int nt = 0; nt < 4; nt++) {
                uint32_t b0 = __float_as_uint(Ks[nt * 8 + g][kk * 8 + q]);
                uint32_t b1 = __float_as_uint(Ks[nt * 8 + g][kk * 8 + q + 4]);
                mma_tf32(s[nt], qa[kk][0], qa[kk][1], qa[kk][2], qa[kk][3], b0, b1);
            }
        }

        // ---- online softmax (rows fully warp-local) ----
        float mxA = -INFINITY, mxB = -INFINITY;
#pragma unroll
        for (int nt = 0; nt < 4; nt++) {
            s[nt][0] *= SCALE; s[nt][1] *= SCALE; s[nt][2] *= SCALE; s[nt][3] *= SCALE;
            mxA = fmaxf(mxA, fmaxf(s[nt][0], s[nt][1]));
            mxB = fmaxf(mxB, fmaxf(s[nt][2], s[nt][3]));
        }
        mxA = fmaxf(mxA, __shfl_xor_sync(FULLM, mxA, 1));
        mxA = fmaxf(mxA, __shfl_xor_sync(FULLM, mxA, 2));
        mxB = fmaxf(mxB, __shfl_xor_sync(FULLM, mxB, 1));
        mxB = fmaxf(mxB, __shfl_xor_sync(FULLM, mxB, 2));

        float mnA = fmaxf(mA, mxA), mnB = fmaxf(mB, mxB);
        float alA = __expf(mA - mnA), alB = __expf(mB - mnB);

        uint32_t p[4][4];
        float suA = 0.0f, suB = 0.0f;
#pragma unroll
        for (int nt = 0; nt < 4; nt++) {
            float p0 = __expf(s[nt][0] - mnA);
            float p1 = __expf(s[nt][1] - mnA);
            float p2 = __expf(s[nt][2] - mnB);
            float p3 = __expf(s[nt][3] - mnB);
            suA += p0 + p1; suB += p2 + p3;
            p[nt][0] = f2tf32(p0); p[nt][1] = f2tf32(p1);
            p[nt][2] = f2tf32(p2); p[nt][3] = f2tf32(p3);
        }
        suA += __shfl_xor_sync(FULLM, suA, 1);
        suA += __shfl_xor_sync(FULLM, suA, 2);
        suB += __shfl_xor_sync(FULLM, suB, 1);
        suB += __shfl_xor_sync(FULLM, suB, 2);
        lA = lA * alA + suA; lB = lB * alB + suB;
        mA = mnA; mB = mnB;
#pragma unroll
        for (int nt = 0; nt < 8; nt++) {
            o[nt][0] *= alA; o[nt][1] *= alA;
            o[nt][2] *= alB; o[nt][3] *= alB;
        }

        // ---- O += P V  (warp tile 16 x 64, K=32 keys) ----
        const int base = lane & ~3;
        const int src0 = base + (q >> 1);
        const int src1 = src0 + 2;
        const bool hi = (q & 1);
#pragma unroll
        for (int kk = 0; kk < 4; kk++) {
            // A fragment of P: permute C-layout -> A-layout within quad
            uint32_t x0 = __shfl_sync(FULLM, p[kk][0], src0);
            uint32_t x1 = __shfl_sync(FULLM, p[kk][1], src0);
            uint32_t a0 = hi ? x1 : x0;
            uint32_t x2 = __shfl_sync(FULLM, p[kk][2], src0);
            uint32_t x3 = __shfl_sync(FULLM, p[kk][3], src0);
            uint32_t a1 = hi ? x3 : x2;
            uint32_t y0 = __shfl_sync(FULLM, p[kk][0], src1);
            uint32_t y1 = __shfl_sync(FULLM, p[kk][1], src1);
            uint32_t a2 = hi ? y1 : y0;
            uint32_t y2 = __shfl_sync(FULLM, p[kk][2], src1);
            uint32_t y3 = __shfl_sync(FULLM, p[kk][3], src1);
            uint32_t a3 = hi ? y3 : y2;
#pragma unroll
            for (int nt = 0; nt < 8; nt++) {
                uint32_t b0 = __float_as_uint(Vs[kk * 8 + q][nt * 8 + g]);
                uint32_t b1 = __float_as_uint(Vs[kk * 8 + q + 4][nt * 8 + g]);
                mma_tf32(o[nt], a0, a1, a2, a3, b0, b1);
            }
        }
    }

    // ---- epilogue ----
    const float ivA = 1.0f / lA, ivB = 1.0f / lB;
    float* Oa = O + (row0 + rowA) * 512 + hc;
    float* Ob = Oa + 8 * 512;
#pragma unroll
    for (int nt = 0; nt < 8; nt++) {
        float2 ra = make_float2(o[nt][0] * ivA, o[nt][1] * ivA);
        float2 rb = make_float2(o[nt][2] * ivB, o[nt][3] * ivB);
        *(float2*)&Oa[nt * 8 + 2 * q] = ra;
        *(float2*)&Ob[nt * 8 + 2 * q] = rb;
    }
}

// ---------------------------------------------------------------------------
// Output GEMM: out[4096,256] = O[4096,512] @ Wo[512,256] + bias
// ---------------------------------------------------------------------------
__global__ __launch_bounds__(256) void outproj_kernel(Ptrs in, float* out) {
    const float* A;
    const float* W;
    const float* bias;
    float* C;
    if (blockIdx.z == 0) { A = g_O1; W = in.p[12]; bias = in.p[13]; C = out; }
    else                 { A = g_O2; W = in.p[14]; bias = in.p[15]; C = out + Nn * 256; }

    __shared__ float As[64][33];
    __shared__ float Ws[32][65];

    const int tid = threadIdx.x;
    const int tx = tid & 15, ty = tid >> 4;
    const int row0 = blockIdx.y * 64;
    const int col0 = blockIdx.x * 64;

    float acc[4][4];
#pragma unroll
    for (int i = 0; i < 4; i++)
#pragma unroll
        for (int j = 0; j < 4; j++) acc[i][j] = 0.0f;

    for (int k0 = 0; k0 < 512; k0 += 32) {
#pragma unroll
        for (int i = tid; i < 64 * 32; i += 256) {
            int r = i >> 5, c = i & 31;
            As[r][c] = A[(row0 + r) * 512 + k0 + c];
        }
#pragma unroll
        for (int i = tid; i < 32 * 64; i += 256) {
            int r = i >> 6, c = i & 63;
            Ws[r][c] = W[(k0 + r) * 256 + col0 + c];
        }
        __syncthreads();
#pragma unroll
        for (int k = 0; k < 32; k++) {
            float a[4], b[4];
#pragma unroll
            for (int i = 0; i < 4; i++) a[i] = As[ty * 4 + i][k];
#pragma unroll
            for (int j = 0; j < 4; j++) b[j] = Ws[k][tx * 4 + j];
#pragma unroll
            for (int i = 0; i < 4; i++)
#pragma unroll
                for (int j = 0; j < 4; j++) acc[i][j] = fmaf(a[i], b[j], acc[i][j]);
        }
        __syncthreads();
    }
#pragma unroll
    for (int j = 0; j < 4; j++) {
        float bb = bias[col0 + tx * 4 + j];
#pragma unroll
        for (int i = 0; i < 4; i++)
            C[(row0 + ty * 4 + i) * 256 + col0 + tx * 4 + j] = acc[i][j] + bb;
    }
}

extern "C" void kernel_launch(void* const* d_in, const int* in_sizes, int n_in,
                              void* d_out, int out_size) {
    Ptrs ptrs;
    for (int i = 0; i < 16; i++) ptrs.p[i] = (const float*)d_in[i];
    float* out = (float*)d_out;

    {
        dim3 grid(512 / 64, Nn / 64, 4);
        proj_kernel<<<grid, 256>>>(ptrs);
    }
    {
        dim3 grid(Nn / 128, NHEADS, 2);
        flash_mma_kernel<<<grid, 256>>>();
    }
    {
        dim3 grid(256 / 64, Nn / 64, 2);
        outproj_kernel<<<grid, 256>>>(ptrs, out);
    }
}

// round 3
// speedup vs baseline: 3.5482x; 1.1309x over previous
#include <cuda_runtime.h>
#include <cuda_bf16.h>
#include <math.h>
#include <stdint.h>

#define Nn 4096
#define NHEADS 8
#define SCALE 0.125f
#define FULLM 0xffffffffu

// Scratch
__device__ float g_K1P[Nn * 512];              // fp32 (tf32-consumed)
__device__ float g_K2P[Nn * 512];
__device__ __nv_bfloat16 g_V1B[Nn * 512];      // bf16 V projections
__device__ __nv_bfloat16 g_V2B[Nn * 512];
__device__ float g_O1[Nn * 512];
__device__ float g_O2[Nn * 512];
__device__ __nv_bfloat16 g_P[(size_t)NHEADS * Nn * Nn];  // 268 MB shared exp(S)
__device__ float g_rsum[NHEADS * Nn];
__device__ float g_csum[NHEADS * Nn];

struct Ptrs {
    const float* p[16];
};

__device__ __forceinline__ uint32_t f2tf32(float x) {
    uint32_t r;
    asm("cvt.rna.tf32.f32 %0, %1;" : "=r"(r) : "f"(x));
    return r;
}

__device__ __forceinline__ void mma_tf32(float c[4],
                                         uint32_t a0, uint32_t a1, uint32_t a2, uint32_t a3,
                                         uint32_t b0, uint32_t b1) {
    asm volatile(
        "mma.sync.aligned.m16n8k8.row.col.f32.tf32.tf32.f32 "
        "{%0,%1,%2,%3}, {%4,%5,%6,%7}, {%8,%9}, {%0,%1,%2,%3};\n"
        : "+f"(c[0]), "+f"(c[1]), "+f"(c[2]), "+f"(c[3])
        : "r"(a0), "r"(a1), "r"(a2), "r"(a3), "r"(b0), "r"(b1));
}

__device__ __forceinline__ void mma_bf16(float c[4],
                                         uint32_t a0, uint32_t a1, uint32_t a2, uint32_t a3,
                                         uint32_t b0, uint32_t b1) {
    asm volatile(
        "mma.sync.aligned.m16n8k16.row.col.f32.bf16.bf16.f32 "
        "{%0,%1,%2,%3}, {%4,%5,%6,%7}, {%8,%9}, {%0,%1,%2,%3};\n"
        : "+f"(c[0]), "+f"(c[1]), "+f"(c[2]), "+f"(c[3])
        : "r"(a0), "r"(a1), "r"(a2), "r"(a3), "r"(b0), "r"(b1));
}

__device__ __forceinline__ void ldm_x4(uint32_t r[4], const void* ptr) {
    uint32_t addr = (uint32_t)__cvta_generic_to_shared(ptr);
    asm volatile("ldmatrix.sync.aligned.m8n8.x4.shared.b16 {%0,%1,%2,%3}, [%4];"
                 : "=r"(r[0]), "=r"(r[1]), "=r"(r[2]), "=r"(r[3]) : "r"(addr));
}

__device__ __forceinline__ void ldm_x4_trans(uint32_t r[4], const void* ptr) {
    uint32_t addr = (uint32_t)__cvta_generic_to_shared(ptr);
    asm volatile("ldmatrix.sync.aligned.m8n8.x4.trans.shared.b16 {%0,%1,%2,%3}, [%4];"
                 : "=r"(r[0]), "=r"(r[1]), "=r"(r[2]), "=r"(r[3]) : "r"(addr));
}

// ---------------------------------------------------------------------------
// zero the softmax denominators
// ---------------------------------------------------------------------------
__global__ void zero_kernel() {
    int i = blockIdx.x * 256 + threadIdx.x;  // 8192 float4 each
    float4 z = make_float4(0.f, 0.f, 0.f, 0.f);
    ((float4*)g_rsum)[i] = z;
    ((float4*)g_csum)[i] = z;
}

// ---------------------------------------------------------------------------
// Projection GEMM: C[4096,512] = A[4096,256] @ W[256,512] + bias
// z=0 -> K1P fp32, z=1 -> V1B bf16, z=2 -> K2P fp32, z=3 -> V2B bf16
// ---------------------------------------------------------------------------
__global__ __launch_bounds__(256) void proj_kernel(Ptrs in) {
    const float *A, *W, *bias;
    float* Cf = nullptr;
    __nv_bfloat16* Cb = nullptr;
    switch (blockIdx.z) {
        case 0: A = in.p[0]; W = in.p[4];  bias = in.p[5];  Cf = g_K1P; break;
        case 1: A = in.p[1]; W = in.p[6];  bias = in.p[7];  Cb = g_V1B; break;
        case 2: A = in.p[2]; W = in.p[8];  bias = in.p[9];  Cf = g_K2P; break;
        default:A = in.p[3]; W = in.p[10]; bias = in.p[11]; Cb = g_V2B; break;
    }
    __shared__ float As[64][33];
    __shared__ float Ws[32][65];

    const int tid = threadIdx.x;
    const int tx = tid & 15, ty = tid >> 4;
    const int row0 = blockIdx.y * 64;
    const int col0 = blockIdx.x * 64;

    float acc[4][4];
#pragma unroll
    for (int i = 0; i < 4; i++)
#pragma unroll
        for (int j = 0; j < 4; j++) acc[i][j] = 0.0f;

    for (int k0 = 0; k0 < 256; k0 += 32) {
#pragma unroll
        for (int i = tid; i < 64 * 32; i += 256) {
            int r = i >> 5, c = i & 31;
            As[r][c] = A[(row0 + r) * 256 + k0 + c];
        }
#pragma unroll
        for (int i = tid; i < 32 * 64; i += 256) {
            int r = i >> 6, c = i & 63;
            Ws[r][c] = W[(k0 + r) * 512 + col0 + c];
        }
        __syncthreads();
#pragma unroll
        for (int k = 0; k < 32; k++) {
            float a[4], b[4];
#pragma unroll
            for (int i = 0; i < 4; i++) a[i] = As[ty * 4 + i][k];
#pragma unroll
            for (int j = 0; j < 4; j++) b[j] = Ws[k][tx * 4 + j];
#pragma unroll
            for (int i = 0; i < 4; i++)
#pragma unroll
                for (int j = 0; j < 4; j++) acc[i][j] = fmaf(a[i], b[j], acc[i][j]);
        }
        __syncthreads();
    }
#pragma unroll
    for (int j = 0; j < 4; j++) {
        float bb = bias[col0 + tx * 4 + j];
#pragma unroll
        for (int i = 0; i < 4; i++) {
            float v = acc[i][j] + bb;
            int idx = (row0 + ty * 4 + i) * 512 + col0 + tx * 4 + j;
            if (Cf) Cf[idx] = v;
            else    Cb[idx] = __float2bfloat16(v);
        }
    }
}

// ---------------------------------------------------------------------------
// Score kernel: S[128n x 128m] = K1p K2p^T (tf32), P = exp(S*scale) -> g_P bf16
// plus row/col sum accumulation (REDG). grid (32 mtiles, 32 ntiles, 8 heads).
// 256 threads = 8 warps in 4(n) x 2(m); warp tile 32n x 64m.
// ---------------------------------------------------------------------------
__global__ __launch_bounds__(256) void score_kernel() {
    extern __shared__ float sm[];
    float* As = sm;                       // [128][68] tf32 (K1p rows)
    float* Bs = sm + 128 * 68;            // [128][68] tf32 (K2p rows)
    uint32_t* PsU = (uint32_t*)(sm + 2 * 128 * 68);  // [128][68] bf16x2 staging

    const int head = blockIdx.z;
    const int n0 = blockIdx.y * 128;
    const int m0 = blockIdx.x * 128;
    const int hc = head * 64;
    const int tid = threadIdx.x;
    const int lane = tid & 31;
    const int wid = tid >> 5;
    const int q = lane & 3, g = lane >> 2;
    const int wn = wid >> 1, wm = wid & 1;
    const int rbase = wn * 32;
    const int cbase = wm * 64;

    // fill A,B tiles (tf32 rounded)
#pragma unroll
    for (int it = 0; it < 8; it++) {
        int j = tid + it * 256;           // 0..2047 float4
        int r = j >> 4, c4 = j & 15;
        float4 av = *(const float4*)&g_K1P[(n0 + r) * 512 + hc + c4 * 4];
        float4 bv = *(const float4*)&g_K2P[(m0 + r) * 512 + hc + c4 * 4];
        float4 ao, bo;
        ao.x = __uint_as_float(f2tf32(av.x)); ao.y = __uint_as_float(f2tf32(av.y));
        ao.z = __uint_as_float(f2tf32(av.z)); ao.w = __uint_as_float(f2tf32(av.w));
        bo.x = __uint_as_float(f2tf32(bv.x)); bo.y = __uint_as_float(f2tf32(bv.y));
        bo.z = __uint_as_float(f2tf32(bv.z)); bo.w = __uint_as_float(f2tf32(bv.w));
        *(float4*)&As[r * 68 + c4 * 4] = ao;
        *(float4*)&Bs[r * 68 + c4 * 4] = bo;
    }
    __syncthreads();

    float cps[8][2];
#pragma unroll
    for (int nt = 0; nt < 8; nt++) { cps[nt][0] = 0.f; cps[nt][1] = 0.f; }

#pragma unroll
    for (int mt = 0; mt < 2; mt++) {
        const int arow = rbase + mt * 16 + g;
        // A fragments for this m16 stripe
        uint32_t af[8][4];
#pragma unroll
        for (int kk = 0; kk < 8; kk++) {
            af[kk][0] = __float_as_uint(As[arow * 68 + kk * 8 + q]);
            af[kk][1] = __float_as_uint(As[(arow + 8) * 68 + kk * 8 + q]);
            af[kk][2] = __float_as_uint(As[arow * 68 + kk * 8 + q + 4]);
            af[kk][3] = __float_as_uint(As[(arow + 8) * 68 + kk * 8 + q + 4]);
        }
        float rp0 = 0.f, rp1 = 0.f;
#pragma unroll
        for (int nt = 0; nt < 8; nt++) {
            float s[4] = {0.f, 0.f, 0.f, 0.f};
            const int brow = cbase + nt * 8 + g;
#pragma unroll
            for (int kk = 0; kk < 8; kk++) {
                uint32_t b0 = __float_as_uint(Bs[brow * 68 + kk * 8 + q]);
                uint32_t b1 = __float_as_uint(Bs[brow * 68 + kk * 8 + q + 4]);
                mma_tf32(s, af[kk][0], af[kk][1], af[kk][2], af[kk][3], b0, b1);
            }
            float p0 = __expf(s[0] * SCALE);
            float p1 = __expf(s[1] * SCALE);
            float p2 = __expf(s[2] * SCALE);
            float p3 = __expf(s[3] * SCALE);
            rp0 += p0 + p1; rp1 += p2 + p3;
            cps[nt][0] += p0 + p2; cps[nt][1] += p1 + p3;
            __nv_bfloat162 h0 = __floats2bfloat162_rn(p0, p1);
            __nv_bfloat162 h1 = __floats2bfloat162_rn(p2, p3);
            int ucol = cbase / 2 + nt * 4 + q;
            PsU[arow * 68 + ucol] = *(uint32_t*)&h0;
            PsU[(arow + 8) * 68 + ucol] = *(uint32_t*)&h1;
        }
        // row sums: reduce over q lanes
        rp0 += __shfl_xor_sync(FULLM, rp0, 1);
        rp0 += __shfl_xor_sync(FULLM, rp0, 2);
        rp1 += __shfl_xor_sync(FULLM, rp1, 1);
        rp1 += __shfl_xor_sync(FULLM, rp1, 2);
        if (q == 0) {
            atomicAdd(&g_rsum[head * Nn + n0 + arow], rp0);
            atomicAdd(&g_rsum[head * Nn + n0 + arow + 8], rp1);
        }
    }

    // col sums: reduce over g lanes
#pragma unroll
    for (int nt = 0; nt < 8; nt++) {
        float v0 = cps[nt][0], v1 = cps[nt][1];
        v0 += __shfl_xor_sync(FULLM, v0, 4);
        v0 += __shfl_xor_sync(FULLM, v0, 8);
        v0 += __shfl_xor_sync(FULLM, v0, 16);
        v1 += __shfl_xor_sync(FULLM, v1, 4);
        v1 += __shfl_xor_sync(FULLM, v1, 8);
        v1 += __shfl_xor_sync(FULLM, v1, 16);
        if (lane < 4) {
            atomicAdd(&g_csum[head * Nn + m0 + cbase + nt * 8 + 2 * q], v0);
            atomicAdd(&g_csum[head * Nn + m0 + cbase + nt * 8 + 2 * q + 1], v1);
        }
    }

    __syncthreads();
    // coalesced write-out of P tile
    {
        int row = tid >> 1, half = tid & 1;
        __nv_bfloat16* dst = g_P + ((size_t)(head * Nn + n0 + row)) * Nn + m0;
#pragma unroll
        for (int i = 0; i < 8; i++) {
            uint4 v = *(uint4*)&PsU[row * 68 + (half + 2 * i) * 4];
            *(uint4*)(dst + (half + 2 * i) * 8) = v;
        }
    }
}

// ---------------------------------------------------------------------------
// o2 = (P @ V2) / rowsum : per head GEMM [4096x4096]x[4096x64], bf16 mma.
// grid (32 row-blocks, 8 heads). Block tile: M=128, N=64, K-chunks of 64.
// ---------------------------------------------------------------------------
__global__ __launch_bounds__(256) void pv_rows_kernel() {
    __shared__ __nv_bfloat16 Ps[128 * 72];
    __shared__ __nv_bfloat16 Vt[64 * 72];   // transposed: [d][k]

    const int head = blockIdx.y;
    const int n0 = blockIdx.x * 128;
    const int hc = head * 64;
    const int tid = threadIdx.x;
    const int lane = tid & 31;
    const int wid = tid >> 5;
    const int q = lane & 3, g = lane >> 2;

    float o[8][4];
#pragma unroll
    for (int dt = 0; dt < 8; dt++)
#pragma unroll
        for (int j = 0; j < 4; j++) o[dt][j] = 0.f;

    // prefetch regs for P tile
    uint4 pbuf[4];
    {
        const int r = tid >> 3, c = tid & 7;  // wait: 1024 uint4 / 256 thr = 4 each
#pragma unroll
        for (int it = 0; it < 4; it++) {
            int j = tid + it * 256;
            int rr = j >> 3, cc = j & 7;
            pbuf[it] = *(const uint4*)(g_P + ((size_t)(head * Nn + n0 + rr)) * Nn + cc * 8);
        }
        (void)r; (void)c;
    }

    for (int kb = 0; kb < Nn / 64; kb++) {
        __syncthreads();
        // store prefetched P tile
#pragma unroll
        for (int it = 0; it < 4; it++) {
            int j = tid + it * 256;
            int rr = j >> 3, cc = j & 7;
            *(uint4*)(Ps + rr * 72 + cc * 8) = pbuf[it];
        }
        // V tile transposed fill
#pragma unroll
        for (int it = 0; it < 16; it++) {
            int j = tid + it * 256;
            int k = j >> 6, d = j & 63;
            Vt[d * 72 + k] = g_V2B[(kb * 64 + k) * 512 + hc + d];
        }
        __syncthreads();
        if (kb + 1 < Nn / 64) {
#pragma unroll
            for (int it = 0; it < 4; it++) {
                int j = tid + it * 256;
                int rr = j >> 3, cc = j & 7;
                pbuf[it] = *(const uint4*)(g_P + ((size_t)(head * Nn + n0 + rr)) * Nn +
                                           (kb + 1) * 64 + cc * 8);
            }
        }
#pragma unroll
        for (int kc = 0; kc < 4; kc++) {
            uint32_t a[4];
            int arow = wid * 16 + (lane & 7) + ((lane >> 3) & 1) * 8;
            int acol = kc * 16 + (lane >> 4) * 8;
            ldm_x4(a, Ps + arow * 72 + acol);
#pragma unroll
            for (int dt = 0; dt < 8; dt++) {
                const uint32_t* vt = (const uint32_t*)(Vt + (dt * 8 + g) * 72 + kc * 16);
                mma_bf16(o[dt], a[0], a[1], a[2], a[3], vt[q], vt[q + 4]);
            }
        }
    }

    const int rA = n0 + wid * 16 + g;
    const float ivA = 1.0f / g_rsum[head * Nn + rA];
    const float ivB = 1.0f / g_rsum[head * Nn + rA + 8];
    float* Oa = g_O2 + rA * 512 + hc;
#pragma unroll
    for (int dt = 0; dt < 8; dt++) {
        *(float2*)&Oa[dt * 8 + 2 * q] = make_float2(o[dt][0] * ivA, o[dt][1] * ivA);
        *(float2*)&Oa[8 * 512 + dt * 8 + 2 * q] = make_float2(o[dt][2] * ivB, o[dt][3] * ivB);
    }
}

// ---------------------------------------------------------------------------
// o1 = (P^T @ V1) / colsum : A = P^T via ldmatrix.trans.
// grid (32 col-blocks, 8 heads). Block tile: M=128 (P cols), K-chunks of 64 rows.
// ---------------------------------------------------------------------------
__global__ __launch_bounds__(256) void pv_cols_kernel() {
    __shared__ __nv_bfloat16 Ps2[64 * 136];  // [k(row of P)][m(col of P)]
    __shared__ __nv_bfloat16 Vt[64 * 72];    // transposed: [d][k]

    const int head = blockIdx.y;
    const int m0 = blockIdx.x * 128;
    const int hc = head * 64;
    const int tid = threadIdx.x;
    const int lane = tid & 31;
    const int wid = tid >> 5;
    const int q = lane & 3, g = lane >> 2;

    float o[8][4];
#pragma unroll
    for (int dt = 0; dt < 8; dt++)
#pragma unroll
        for (int j = 0; j < 4; j++) o[dt][j] = 0.f;

    uint4 pbuf[4];
#pragma unroll
    for (int it = 0; it < 4; it++) {
        int j = tid + it * 256;
        int rr = j >> 4, cc = j & 15;
        pbuf[it] = *(const uint4*)(g_P + ((size_t)(head * Nn + rr)) * Nn + m0 + cc * 8);
    }

    for (int kb = 0; kb < Nn / 64; kb++) {
        __syncthreads();
#pragma unroll
        for (int it = 0; it < 4; it++) {
            int j = tid + it * 256;
            int rr = j >> 4, cc = j & 15;
            *(uint4*)(Ps2 + rr * 136 + cc * 8) = pbuf[it];
        }
#pragma unroll
        for (int it = 0; it < 16; it++) {
            int j = tid + it * 256;
            int k = j >> 6, d = j & 63;
            Vt[d * 72 + k] = g_V1B[(kb * 64 + k) * 512 + hc + d];
        }
        __syncthreads();
        if (kb + 1 < Nn / 64) {
#pragma unroll
            for (int it = 0; it < 4; it++) {
                int j = tid + it * 256;
                int rr = j >> 4, cc = j & 15;
                pbuf[it] = *(const uint4*)(g_P + ((size_t)(head * Nn + (kb + 1) * 64 + rr)) * Nn +
                                           m0 + cc * 8);
            }
        }
#pragma unroll
        for (int kc = 0; kc < 4; kc++) {
            uint32_t a[4];
            int krow = kc * 16 + (lane & 7) + ((lane >> 4) & 1) * 8;
            int mcol = wid * 16 + ((lane >> 3) & 1) * 8;
            ldm_x4_trans(a, Ps2 + krow * 136 + mcol);
#pragma unroll
            for (int dt = 0; dt < 8; dt++) {
                const uint32_t* vt = (const uint32_t*)(Vt + (dt * 8 + g) * 72 + kc * 16);
                mma_bf16(o[dt], a[0], a[1], a[2], a[3], vt[q], vt[q + 4]);
            }
        }
    }

    const int rA = m0 + wid * 16 + g;
    const float ivA = 1.0f / g_csum[head * Nn + rA];
    const float ivB = 1.0f / g_csum[head * Nn + rA + 8];
    float* Oa = g_O1 + rA * 512 + hc;
#pragma unroll
    for (int dt = 0; dt < 8; dt++) {
        *(float2*)&Oa[dt * 8 + 2 * q] = make_float2(o[dt][0] * ivA, o[dt][1] * ivA);
        *(float2*)&Oa[8 * 512 + dt * 8 + 2 * q] = make_float2(o[dt][2] * ivB, o[dt][3] * ivB);
    }
}

// ---------------------------------------------------------------------------
// Output GEMM: out[4096,256] = O[4096,512] @ Wo[512,256] + bias
// ---------------------------------------------------------------------------
__global__ __launch_bounds__(256) void outproj_kernel(Ptrs in, float* out) {
    const float* A;
    const float* W;
    const float* bias;
    float* C;
    if (blockIdx.z == 0) { A = g_O1; W = in.p[12]; bias = in.p[13]; C = out; }
    else                 { A = g_O2; W = in.p[14]; bias = in.p[15]; C = out + Nn * 256; }

    __shared__ float As[64][33];
    __shared__ float Ws[32][65];

    const int tid = threadIdx.x;
    const int tx = tid & 15, ty = tid >> 4;
    const int row0 = blockIdx.y * 64;
    const int col0 = blockIdx.x * 64;

    float acc[4][4];
#pragma unroll
    for (int i = 0; i < 4; i++)
#pragma unroll
        for (int j = 0; j < 4; j++) acc[i][j] = 0.0f;

    for (int k0 = 0; k0 < 512; k0 += 32) {
#pragma unroll
        for (int i = tid; i < 64 * 32; i += 256) {
            int r = i >> 5, c = i & 31;
            As[r][c] = A[(row0 + r) * 512 + k0 + c];
        }
#pragma unroll
        for (int i = tid; i < 32 * 64; i += 256) {
            int r = i >> 6, c = i & 63;
            Ws[r][c] = W[(k0 + r) * 256 + col0 + c];
        }
        __syncthreads();
#pragma unroll
        for (int k = 0; k < 32; k++) {
            float a[4], b[4];
#pragma unroll
            for (int i = 0; i < 4; i++) a[i] = As[ty * 4 + i][k];
#pragma unroll
            for (int j = 0; j < 4; j++) b[j] = Ws[k][tx * 4 + j];
#pragma unroll
            for (int i = 0; i < 4; i++)
#pragma unroll
                for (int j = 0; j < 4; j++) acc[i][j] = fmaf(a[i], b[j], acc[i][j]);
        }
        __syncthreads();
    }
#pragma unroll
    for (int j = 0; j < 4; j++) {
        float bb = bias[col0 + tx * 4 + j];
#pragma unroll
        for (int i = 0; i < 4; i++)
            C[(row0 + ty * 4 + i) * 256 + col0 + tx * 4 + j] = acc[i][j] + bb;
    }
}

extern "C" void kernel_launch(void* const* d_in, const int* in_sizes, int n_in,
                              void* d_out, int out_size) {
    Ptrs ptrs;
    for (int i = 0; i < 16; i++) ptrs.p[i] = (const float*)d_in[i];
    float* out = (float*)d_out;

    static bool attr_done = false;
    if (!attr_done) {
        cudaFuncSetAttribute(score_kernel, cudaFuncAttributeMaxDynamicSharedMemorySize,
                             3 * 128 * 68 * 4);
        attr_done = true;
    }

    zero_kernel<<<32, 256>>>();
    {
        dim3 grid(512 / 64, Nn / 64, 4);
        proj_kernel<<<grid, 256>>>(ptrs);
    }
    {
        dim3 grid(Nn / 128, Nn / 128, NHEADS);
        score_kernel<<<grid, 256, 3 * 128 * 68 * 4>>>();
    }
    {
        dim3 grid(Nn / 128, NHEADS);
        pv_rows_kernel<<<grid, 256>>>();
        pv_cols_kernel<<<grid, 256>>>();
    }
    {
        dim3 grid(256 / 64, Nn / 64, 2);
        outproj_kernel<<<grid, 256>>>(ptrs, out);
    }
}

// round 4
// speedup vs baseline: 4.7451x; 1.3373x over previous
#include <cuda_runtime.h>
#include <cuda_bf16.h>
#include <math.h>
#include <stdint.h>

#define Nn 4096
#define NHEADS 8
#define SCALE 0.125f
#define FULLM 0xffffffffu

// Scratch
__device__ float g_K1P[Nn * 512];              // fp32 (tf32-consumed)
__device__ float g_K2P[Nn * 512];
__device__ __nv_bfloat16 g_V1B[Nn * 512];      // bf16 V projections
__device__ __nv_bfloat16 g_V2B[Nn * 512];
__device__ float g_O1[Nn * 512];
__device__ float g_O2[Nn * 512];
__device__ __nv_bfloat16 g_P[(size_t)NHEADS * Nn * Nn];  // 268 MB shared exp(S)
__device__ float g_rsum[NHEADS * Nn];
__device__ float g_csum[NHEADS * Nn];

struct Ptrs {
    const float* p[16];
};

__device__ __forceinline__ uint32_t f2tf32(float x) {
    uint32_t r;
    asm("cvt.rna.tf32.f32 %0, %1;" : "=r"(r) : "f"(x));
    return r;
}

__device__ __forceinline__ void mma_tf32(float c[4],
                                         uint32_t a0, uint32_t a1, uint32_t a2, uint32_t a3,
                                         uint32_t b0, uint32_t b1) {
    asm volatile(
        "mma.sync.aligned.m16n8k8.row.col.f32.tf32.tf32.f32 "
        "{%0,%1,%2,%3}, {%4,%5,%6,%7}, {%8,%9}, {%0,%1,%2,%3};\n"
        : "+f"(c[0]), "+f"(c[1]), "+f"(c[2]), "+f"(c[3])
        : "r"(a0), "r"(a1), "r"(a2), "r"(a3), "r"(b0), "r"(b1));
}

__device__ __forceinline__ void mma_bf16(float c[4],
                                         uint32_t a0, uint32_t a1, uint32_t a2, uint32_t a3,
                                         uint32_t b0, uint32_t b1) {
    asm volatile(
        "mma.sync.aligned.m16n8k16.row.col.f32.bf16.bf16.f32 "
        "{%0,%1,%2,%3}, {%4,%5,%6,%7}, {%8,%9}, {%0,%1,%2,%3};\n"
        : "+f"(c[0]), "+f"(c[1]), "+f"(c[2]), "+f"(c[3])
        : "r"(a0), "r"(a1), "r"(a2), "r"(a3), "r"(b0), "r"(b1));
}

__device__ __forceinline__ void ldm_x4(uint32_t r[4], const void* ptr) {
    uint32_t addr = (uint32_t)__cvta_generic_to_shared(ptr);
    asm volatile("ldmatrix.sync.aligned.m8n8.x4.shared.b16 {%0,%1,%2,%3}, [%4];"
                 : "=r"(r[0]), "=r"(r[1]), "=r"(r[2]), "=r"(r[3]) : "r"(addr));
}

__device__ __forceinline__ void ldm_x4_trans(uint32_t r[4], const void* ptr) {
    uint32_t addr = (uint32_t)__cvta_generic_to_shared(ptr);
    asm volatile("ldmatrix.sync.aligned.m8n8.x4.trans.shared.b16 {%0,%1,%2,%3}, [%4];"
                 : "=r"(r[0]), "=r"(r[1]), "=r"(r[2]), "=r"(r[3]) : "r"(addr));
}

__device__ __forceinline__ void cp16(void* smem_dst, const void* gsrc) {
    uint32_t d = (uint32_t)__cvta_generic_to_shared(smem_dst);
    asm volatile("cp.async.cg.shared.global [%0], [%1], 16;" :: "r"(d), "l"(gsrc));
}

// ---------------------------------------------------------------------------
// zero the softmax denominators
// ---------------------------------------------------------------------------
__global__ void zero_kernel() {
    int i = blockIdx.x * 256 + threadIdx.x;
    float4 z = make_float4(0.f, 0.f, 0.f, 0.f);
    ((float4*)g_rsum)[i] = z;
    ((float4*)g_csum)[i] = z;
}

// ---------------------------------------------------------------------------
// Projection GEMM (tf32 mma): C[4096,512] = A[4096,256] @ W[256,512] + bias
// grid (512/64, 4096/128, 4), 256 threads = 8 warps, warp tile 16x64.
// z=0 -> K1P fp32, z=1 -> V1B bf16, z=2 -> K2P fp32, z=3 -> V2B bf16
// ---------------------------------------------------------------------------
__global__ __launch_bounds__(256) void proj_mma_kernel(Ptrs in) {
    const float *A, *W, *bias;
    float* Cf = nullptr;
    __nv_bfloat16* Cb = nullptr;
    switch (blockIdx.z) {
        case 0: A = in.p[0]; W = in.p[4];  bias = in.p[5];  Cf = g_K1P; break;
        case 1: A = in.p[1]; W = in.p[6];  bias = in.p[7];  Cb = g_V1B; break;
        case 2: A = in.p[2]; W = in.p[8];  bias = in.p[9];  Cf = g_K2P; break;
        default:A = in.p[3]; W = in.p[10]; bias = in.p[11]; Cb = g_V2B; break;
    }
    __shared__ float As[128 * 36];   // [row][k] pad 36
    __shared__ float Ws[32 * 68];    // [k][n]  pad 68

    const int tid = threadIdx.x;
    const int lane = tid & 31, wid = tid >> 5;
    const int q = lane & 3, g = lane >> 2;
    const int row0 = blockIdx.y * 128;
    const int col0 = blockIdx.x * 64;

    float o[8][4];
#pragma unroll
    for (int nt = 0; nt < 8; nt++)
#pragma unroll
        for (int j = 0; j < 4; j++) o[nt][j] = 0.f;

    for (int k0 = 0; k0 < 256; k0 += 32) {
        __syncthreads();
#pragma unroll
        for (int it = 0; it < 4; it++) {
            int j = tid + it * 256;            // float4 idx 0..1023
            int rr = j >> 3, cc = j & 7;
            float4 v = *(const float4*)&A[(row0 + rr) * 256 + k0 + cc * 4];
            v.x = __uint_as_float(f2tf32(v.x)); v.y = __uint_as_float(f2tf32(v.y));
            v.z = __uint_as_float(f2tf32(v.z)); v.w = __uint_as_float(f2tf32(v.w));
            *(float4*)&As[rr * 36 + cc * 4] = v;
        }
#pragma unroll
        for (int it = 0; it < 2; it++) {
            int j = tid + it * 256;            // 0..511
            int rr = j >> 4, cc = j & 15;
            float4 v = *(const float4*)&W[(k0 + rr) * 512 + col0 + cc * 4];
            v.x = __uint_as_float(f2tf32(v.x)); v.y = __uint_as_float(f2tf32(v.y));
            v.z = __uint_as_float(f2tf32(v.z)); v.w = __uint_as_float(f2tf32(v.w));
            *(float4*)&Ws[rr * 68 + cc * 4] = v;
        }
        __syncthreads();
#pragma unroll
        for (int kk = 0; kk < 4; kk++) {
            const int ar = wid * 16 + g;
            uint32_t a0 = __float_as_uint(As[ar * 36 + kk * 8 + q]);
            uint32_t a1 = __float_as_uint(As[(ar + 8) * 36 + kk * 8 + q]);
            uint32_t a2 = __float_as_uint(As[ar * 36 + kk * 8 + q + 4]);
            uint32_t a3 = __float_as_uint(As[(ar + 8) * 36 + kk * 8 + q + 4]);
#pragma unroll
            for (int nt = 0; nt < 8; nt++) {
                uint32_t b0 = __float_as_uint(Ws[(kk * 8 + q) * 68 + nt * 8 + g]);
                uint32_t b1 = __float_as_uint(Ws[(kk * 8 + q + 4) * 68 + nt * 8 + g]);
                mma_tf32(o[nt], a0, a1, a2, a3, b0, b1);
            }
        }
    }

    const int r = row0 + wid * 16 + g;
#pragma unroll
    for (int nt = 0; nt < 8; nt++) {
        int c = col0 + nt * 8 + 2 * q;
        float b0 = bias[c], b1 = bias[c + 1];
        float v00 = o[nt][0] + b0, v01 = o[nt][1] + b1;
        float v10 = o[nt][2] + b0, v11 = o[nt][3] + b1;
        if (Cf) {
            *(float2*)&Cf[r * 512 + c] = make_float2(v00, v01);
            *(float2*)&Cf[(r + 8) * 512 + c] = make_float2(v10, v11);
        } else {
            __nv_bfloat162 h0 = __floats2bfloat162_rn(v00, v01);
            __nv_bfloat162 h1 = __floats2bfloat162_rn(v10, v11);
            *(uint32_t*)&Cb[r * 512 + c] = *(uint32_t*)&h0;
            *(uint32_t*)&Cb[(r + 8) * 512 + c] = *(uint32_t*)&h1;
        }
    }
}

// ---------------------------------------------------------------------------
// Score kernel: S[128n x 128m] = K1p K2p^T (tf32), P = exp(S*scale) -> g_P bf16
// plus row/col sum accumulation. grid (32, 32, 8).
// ---------------------------------------------------------------------------
__global__ __launch_bounds__(256) void score_kernel() {
    extern __shared__ float sm[];
    float* As = sm;                       // [128][68]
    float* Bs = sm + 128 * 68;            // [128][68]
    uint32_t* PsU = (uint32_t*)(sm + 2 * 128 * 68);  // [128][68] bf16x2

    const int head = blockIdx.z;
    const int n0 = blockIdx.y * 128;
    const int m0 = blockIdx.x * 128;
    const int hc = head * 64;
    const int tid = threadIdx.x;
    const int lane = tid & 31;
    const int wid = tid >> 5;
    const int q = lane & 3, g = lane >> 2;
    const int wn = wid >> 1, wm = wid & 1;
    const int rbase = wn * 32;
    const int cbase = wm * 64;

#pragma unroll
    for (int it = 0; it < 8; it++) {
        int j = tid + it * 256;
        int r = j >> 4, c4 = j & 15;
        float4 av = *(const float4*)&g_K1P[(n0 + r) * 512 + hc + c4 * 4];
        float4 bv = *(const float4*)&g_K2P[(m0 + r) * 512 + hc + c4 * 4];
        float4 ao, bo;
        ao.x = __uint_as_float(f2tf32(av.x)); ao.y = __uint_as_float(f2tf32(av.y));
        ao.z = __uint_as_float(f2tf32(av.z)); ao.w = __uint_as_float(f2tf32(av.w));
        bo.x = __uint_as_float(f2tf32(bv.x)); bo.y = __uint_as_float(f2tf32(bv.y));
        bo.z = __uint_as_float(f2tf32(bv.z)); bo.w = __uint_as_float(f2tf32(bv.w));
        *(float4*)&As[r * 68 + c4 * 4] = ao;
        *(float4*)&Bs[r * 68 + c4 * 4] = bo;
    }
    __syncthreads();

    float cps[8][2];
#pragma unroll
    for (int nt = 0; nt < 8; nt++) { cps[nt][0] = 0.f; cps[nt][1] = 0.f; }

#pragma unroll
    for (int mt = 0; mt < 2; mt++) {
        const int arow = rbase + mt * 16 + g;
        uint32_t af[8][4];
#pragma unroll
        for (int kk = 0; kk < 8; kk++) {
            af[kk][0] = __float_as_uint(As[arow * 68 + kk * 8 + q]);
            af[kk][1] = __float_as_uint(As[(arow + 8) * 68 + kk * 8 + q]);
            af[kk][2] = __float_as_uint(As[arow * 68 + kk * 8 + q + 4]);
            af[kk][3] = __float_as_uint(As[(arow + 8) * 68 + kk * 8 + q + 4]);
        }
        float rp0 = 0.f, rp1 = 0.f;
#pragma unroll
        for (int nt = 0; nt < 8; nt++) {
            float s[4] = {0.f, 0.f, 0.f, 0.f};
            const int brow = cbase + nt * 8 + g;
#pragma unroll
            for (int kk = 0; kk < 8; kk++) {
                uint32_t b0 = __float_as_uint(Bs[brow * 68 + kk * 8 + q]);
                uint32_t b1 = __float_as_uint(Bs[brow * 68 + kk * 8 + q + 4]);
                mma_tf32(s, af[kk][0], af[kk][1], af[kk][2], af[kk][3], b0, b1);
            }
            float p0 = __expf(s[0] * SCALE);
            float p1 = __expf(s[1] * SCALE);
            float p2 = __expf(s[2] * SCALE);
            float p3 = __expf(s[3] * SCALE);
            rp0 += p0 + p1; rp1 += p2 + p3;
            cps[nt][0] += p0 + p2; cps[nt][1] += p1 + p3;
            __nv_bfloat162 h0 = __floats2bfloat162_rn(p0, p1);
            __nv_bfloat162 h1 = __floats2bfloat162_rn(p2, p3);
            int ucol = cbase / 2 + nt * 4 + q;
            PsU[arow * 68 + ucol] = *(uint32_t*)&h0;
            PsU[(arow + 8) * 68 + ucol] = *(uint32_t*)&h1;
        }
        rp0 += __shfl_xor_sync(FULLM, rp0, 1);
        rp0 += __shfl_xor_sync(FULLM, rp0, 2);
        rp1 += __shfl_xor_sync(FULLM, rp1, 1);
        rp1 += __shfl_xor_sync(FULLM, rp1, 2);
        if (q == 0) {
            atomicAdd(&g_rsum[head * Nn + n0 + arow], rp0);
            atomicAdd(&g_rsum[head * Nn + n0 + arow + 8], rp1);
        }
    }

#pragma unroll
    for (int nt = 0; nt < 8; nt++) {
        float v0 = cps[nt][0], v1 = cps[nt][1];
        v0 += __shfl_xor_sync(FULLM, v0, 4);
        v0 += __shfl_xor_sync(FULLM, v0, 8);
        v0 += __shfl_xor_sync(FULLM, v0, 16);
        v1 += __shfl_xor_sync(FULLM, v1, 4);
        v1 += __shfl_xor_sync(FULLM, v1, 8);
        v1 += __shfl_xor_sync(FULLM, v1, 16);
        if (lane < 4) {
            atomicAdd(&g_csum[head * Nn + m0 + cbase + nt * 8 + 2 * q], v0);
            atomicAdd(&g_csum[head * Nn + m0 + cbase + nt * 8 + 2 * q + 1], v1);
        }
    }

    __syncthreads();
    {
        int row = tid >> 1, half = tid & 1;
        __nv_bfloat16* dst = g_P + ((size_t)(head * Nn + n0 + row)) * Nn + m0;
#pragma unroll
        for (int i = 0; i < 8; i++) {
            uint4 v = *(uint4*)&PsU[row * 68 + (half + 2 * i) * 4];
            *(uint4*)(dst + (half + 2 * i) * 8) = v;
        }
    }
}

// ---------------------------------------------------------------------------
// Fused PV kernel: grid (32, 8, 2), 256 threads.
//   z=0: o2 = (P @ V2)/rsum    — A = P row-strip (ldmatrix), B = V2 (ldm.trans)
//   z=1: o1 = (P^T @ V1)/csum  — A = P^T (ldm.trans),        B = V1 (ldm.trans)
// 2-stage cp.async pipeline, K-chunks of 64.
// ---------------------------------------------------------------------------
#define PV_PSTRIDE 9216   // bf16 elems per P stage (max of 128*72, 64*136)
#define PV_VSTRIDE 4608   // 64*72
#define PV_KT 64

__global__ __launch_bounds__(256) void pv_kernel() {
    extern __shared__ __nv_bfloat16 smp[];
    __nv_bfloat16* Pb = smp;                       // 2 stages
    __nv_bfloat16* Vb = smp + 2 * PV_PSTRIDE;      // 2 stages

    const int head = blockIdx.y;
    const int blk0 = blockIdx.x * 128;             // n0 (z=0) or m0 (z=1)
    const int hc = head * 64;
    const int dir = blockIdx.z;
    const int tid = threadIdx.x;
    const int lane = tid & 31, wid = tid >> 5;
    const int q = lane & 3, g = lane >> 2;

    const __nv_bfloat16* Vg = dir ? g_V1B : g_V2B;

    float o[8][4];
#pragma unroll
    for (int dt = 0; dt < 8; dt++)
#pragma unroll
        for (int j = 0; j < 4; j++) o[dt][j] = 0.f;

    auto issue = [&](int kb, int buf) {
        __nv_bfloat16* Pd = Pb + buf * PV_PSTRIDE;
        __nv_bfloat16* Vd = Vb + buf * PV_VSTRIDE;
        if (dir == 0) {
            // P[128 n-rows][64 k-cols], smem stride 72
#pragma unroll
            for (int it = 0; it < 4; it++) {
                int j = tid + it * 256;
                int rr = j >> 3, cc = j & 7;
                cp16(Pd + rr * 72 + cc * 8,
                     g_P + ((size_t)(head * Nn + blk0 + rr)) * Nn + kb * 64 + cc * 8);
            }
        } else {
            // P[64 k-rows][128 m-cols], smem stride 136
#pragma unroll
            for (int it = 0; it < 4; it++) {
                int j = tid + it * 256;
                int rr = j >> 4, cc = j & 15;
                cp16(Pd + rr * 136 + cc * 8,
                     g_P + ((size_t)(head * Nn + kb * 64 + rr)) * Nn + blk0 + cc * 8);
            }
        }
        // V[64 k][64 d], smem stride 72
#pragma unroll
        for (int it = 0; it < 2; it++) {
            int j = tid + it * 256;
            int rr = j >> 3, cc = j & 7;
            cp16(Vd + rr * 72 + cc * 8, Vg + (kb * 64 + rr) * 512 + hc + cc * 8);
        }
        asm volatile("cp.async.commit_group;" ::: "memory");
    };

    issue(0, 0);
    issue(1, 1);

    for (int kb = 0; kb < PV_KT; kb++) {
        if (kb == PV_KT - 1) asm volatile("cp.async.wait_group 0;" ::: "memory");
        else                 asm volatile("cp.async.wait_group 1;" ::: "memory");
        __syncthreads();

        const __nv_bfloat16* Pc = Pb + (kb & 1) * PV_PSTRIDE;
        const __nv_bfloat16* Vc = Vb + (kb & 1) * PV_VSTRIDE;

        const int brow = ((lane >> 3) & 1) * 8 + (lane & 7);
        const int bcoff = (lane >> 4) * 8;

#pragma unroll
        for (int kc = 0; kc < 4; kc++) {
            uint32_t a[4];
            if (dir == 0) {
                int arow = wid * 16 + (lane & 7) + ((lane >> 3) & 1) * 8;
                int acol = kc * 16 + (lane >> 4) * 8;
                ldm_x4(a, Pc + arow * 72 + acol);
            } else {
                int krow = kc * 16 + (lane & 7) + ((lane >> 4) & 1) * 8;
                int mcol = wid * 16 + ((lane >> 3) & 1) * 8;
                ldm_x4_trans(a, Pc + krow * 136 + mcol);
            }
#pragma unroll
            for (int dtp = 0; dtp < 4; dtp++) {
                uint32_t b[4];
                ldm_x4_trans(b, Vc + (kc * 16 + brow) * 72 + dtp * 16 + bcoff);
                mma_bf16(o[2 * dtp],     a[0], a[1], a[2], a[3], b[0], b[1]);
                mma_bf16(o[2 * dtp + 1], a[0], a[1], a[2], a[3], b[2], b[3]);
            }
        }
        __syncthreads();
        if (kb + 2 < PV_KT) issue(kb + 2, kb & 1);
    }

    const int rA = blk0 + wid * 16 + g;
    const float* nrm = dir ? g_csum : g_rsum;
    const float ivA = 1.0f / nrm[head * Nn + rA];
    const float ivB = 1.0f / nrm[head * Nn + rA + 8];
    float* Og = (dir ? g_O1 : g_O2) + rA * 512 + hc;
#pragma unroll
    for (int dt = 0; dt < 8; dt++) {
        *(float2*)&Og[dt * 8 + 2 * q] = make_float2(o[dt][0] * ivA, o[dt][1] * ivA);
        *(float2*)&Og[8 * 512 + dt * 8 + 2 * q] = make_float2(o[dt][2] * ivB, o[dt][3] * ivB);
    }
}

// ---------------------------------------------------------------------------
// Output GEMM: out[4096,256] = O[4096,512] @ Wo[512,256] + bias (fp32 exact)
// ---------------------------------------------------------------------------
__global__ __launch_bounds__(256) void outproj_kernel(Ptrs in, float* out) {
    const float* A;
    const float* W;
    const float* bias;
    float* C;
    if (blockIdx.z == 0) { A = g_O1; W = in.p[12]; bias = in.p[13]; C = out; }
    else                 { A = g_O2; W = in.p[14]; bias = in.p[15]; C = out + Nn * 256; }

    __shared__ float As[64][33];
    __shared__ float Ws[32][65];

    const int tid = threadIdx.x;
    const int tx = tid & 15, ty = tid >> 4;
    const int row0 = blockIdx.y * 64;
    const int col0 = blockIdx.x * 64;

    float acc[4][4];
#pragma unroll
    for (int i = 0; i < 4; i++)
#pragma unroll
        for (int j = 0; j < 4; j++) acc[i][j] = 0.0f;

    for (int k0 = 0; k0 < 512; k0 += 32) {
#pragma unroll
        for (int i = tid; i < 64 * 32; i += 256) {
            int r = i >> 5, c = i & 31;
            As[r][c] = A[(row0 + r) * 512 + k0 + c];
        }
#pragma unroll
        for (int i = tid; i < 32 * 64; i += 256) {
            int r = i >> 6, c = i & 63;
            Ws[r][c] = W[(k0 + r) * 256 + col0 + c];
        }
        __syncthreads();
#pragma unroll
        for (int k = 0; k < 32; k++) {
            float a[4], b[4];
#pragma unroll
            for (int i = 0; i < 4; i++) a[i] = As[ty * 4 + i][k];
#pragma unroll
            for (int j = 0; j < 4; j++) b[j] = Ws[k][tx * 4 + j];
#pragma unroll
            for (int i = 0; i < 4; i++)
#pragma unroll
                for (int j = 0; j < 4; j++) acc[i][j] = fmaf(a[i], b[j], acc[i][j]);
        }
        __syncthreads();
    }
#pragma unroll
    for (int j = 0; j < 4; j++) {
        float bb = bias[col0 + tx * 4 + j];
#pragma unroll
        for (int i = 0; i < 4; i++)
            C[(row0 + ty * 4 + i) * 256 + col0 + tx * 4 + j] = acc[i][j] + bb;
    }
}

extern "C" void kernel_launch(void* const* d_in, const int* in_sizes, int n_in,
                              void* d_out, int out_size) {
    Ptrs ptrs;
    for (int i = 0; i < 16; i++) ptrs.p[i] = (const float*)d_in[i];
    float* out = (float*)d_out;

    cudaFuncSetAttribute(score_kernel, cudaFuncAttributeMaxDynamicSharedMemorySize,
                         3 * 128 * 68 * 4);
    cudaFuncSetAttribute(pv_kernel, cudaFuncAttributeMaxDynamicSharedMemorySize,
                         (2 * PV_PSTRIDE + 2 * PV_VSTRIDE) * 2);

    zero_kernel<<<32, 256>>>();
    {
        dim3 grid(512 / 64, Nn / 128, 4);
        proj_mma_kernel<<<grid, 256>>>(ptrs);
    }
    {
        dim3 grid(Nn / 128, Nn / 128, NHEADS);
        score_kernel<<<grid, 256, 3 * 128 * 68 * 4>>>();
    }
    {
        dim3 grid(Nn / 128, NHEADS, 2);
        pv_kernel<<<grid, 256, (2 * PV_PSTRIDE + 2 * PV_VSTRIDE) * 2>>>();
    }
    {
        dim3 grid(256 / 64, Nn / 64, 2);
        outproj_kernel<<<grid, 256>>>(ptrs, out);
    }
}

// round 6
// speedup vs baseline: 7.3483x; 1.5486x over previous
#include <cuda_runtime.h>
#include <cuda_fp16.h>
#include <math.h>
#include <stdint.h>

#define Nn 4096
#define NHEADS 8
#define SCALE 0.125f
#define FULLM 0xffffffffu

// fp16 scratch
__device__ __half g_K1H[Nn * 512];
__device__ __half g_K2H[Nn * 512];
__device__ __half g_V1H[Nn * 512];
__device__ __half g_V2H[Nn * 512];
__device__ __half g_Ph[(size_t)NHEADS * Nn * Nn];      // 268 MB exp(S)
__device__ __half g_Op[4][(size_t)Nn * 512];           // partial O: [dir*2+ks]
__device__ float g_rsum[NHEADS * Nn];
__device__ float g_csum[NHEADS * Nn];

struct Ptrs {
    const float* p[16];
};

__device__ __forceinline__ void mma_f16(float c[4],
                                        uint32_t a0, uint32_t a1, uint32_t a2, uint32_t a3,
                                        uint32_t b0, uint32_t b1) {
    asm volatile(
        "mma.sync.aligned.m16n8k16.row.col.f32.f16.f16.f32 "
        "{%0,%1,%2,%3}, {%4,%5,%6,%7}, {%8,%9}, {%0,%1,%2,%3};\n"
        : "+f"(c[0]), "+f"(c[1]), "+f"(c[2]), "+f"(c[3])
        : "r"(a0), "r"(a1), "r"(a2), "r"(a3), "r"(b0), "r"(b1));
}

__device__ __forceinline__ void ldm_x4(uint32_t r[4], const void* ptr) {
    uint32_t addr = (uint32_t)__cvta_generic_to_shared(ptr);
    asm volatile("ldmatrix.sync.aligned.m8n8.x4.shared.b16 {%0,%1,%2,%3}, [%4];"
                 : "=r"(r[0]), "=r"(r[1]), "=r"(r[2]), "=r"(r[3]) : "r"(addr));
}

__device__ __forceinline__ void ldm_x4_trans(uint32_t r[4], const void* ptr) {
    uint32_t addr = (uint32_t)__cvta_generic_to_shared(ptr);
    asm volatile("ldmatrix.sync.aligned.m8n8.x4.trans.shared.b16 {%0,%1,%2,%3}, [%4];"
                 : "=r"(r[0]), "=r"(r[1]), "=r"(r[2]), "=r"(r[3]) : "r"(addr));
}

__device__ __forceinline__ void cp16(void* smem_dst, const void* gsrc) {
    uint32_t d = (uint32_t)__cvta_generic_to_shared(smem_dst);
    asm volatile("cp.async.cg.shared.global [%0], [%1], 16;" :: "r"(d), "l"(gsrc));
}

__device__ __forceinline__ uint4 pack8h(float4 v0, float4 v1) {
    uint4 u;
    __half2* h = (__half2*)&u;
    h[0] = __floats2half2_rn(v0.x, v0.y);
    h[1] = __floats2half2_rn(v0.z, v0.w);
    h[2] = __floats2half2_rn(v1.x, v1.y);
    h[3] = __floats2half2_rn(v1.z, v1.w);
    return u;
}

// ---------------------------------------------------------------------------
// zero the softmax denominators
// ---------------------------------------------------------------------------
__global__ void zero_kernel() {
    int i = blockIdx.x * 256 + threadIdx.x;
    float4 z = make_float4(0.f, 0.f, 0.f, 0.f);
    ((float4*)g_rsum)[i] = z;
    ((float4*)g_csum)[i] = z;
}

// in-place reciprocal of the accumulated sums
__global__ void recip_kernel() {
    int i = blockIdx.x * 256 + threadIdx.x;   // 32768 total
    g_rsum[i] = 1.0f / g_rsum[i];
    g_csum[i] = 1.0f / g_csum[i];
}

// ---------------------------------------------------------------------------
// Projection (fp16 mma): C[4096,512] = A[4096,256] @ W[256,512] + bias -> fp16
// grid (8, 32, 4), 256 thr, block tile 128x64, k-chunks 64.
// ---------------------------------------------------------------------------
__global__ __launch_bounds__(256) void proj_f16_kernel(Ptrs in) {
    const float *A, *W, *bias;
    __half* C;
    switch (blockIdx.z) {
        case 0: A = in.p[0]; W = in.p[4];  bias = in.p[5];  C = g_K1H; break;
        case 1: A = in.p[1]; W = in.p[6];  bias = in.p[7];  C = g_V1H; break;
        case 2: A = in.p[2]; W = in.p[8];  bias = in.p[9];  C = g_K2H; break;
        default:A = in.p[3]; W = in.p[10]; bias = in.p[11]; C = g_V2H; break;
    }
    __shared__ __half As[128 * 72];
    __shared__ __half Ws[64 * 72];

    const int tid = threadIdx.x;
    const int lane = tid & 31, wid = tid >> 5;
    const int q = lane & 3, g = lane >> 2;
    const int row0 = blockIdx.y * 128;
    const int col0 = blockIdx.x * 64;
    const int brow = ((lane >> 3) & 1) * 8 + (lane & 7);
    const int bcoff = (lane >> 4) * 8;
    const int arow = wid * 16 + (lane & 7) + ((lane >> 3) & 1) * 8;
    const int acoff = (lane >> 4) * 8;

    float o[8][4];
#pragma unroll
    for (int nt = 0; nt < 8; nt++)
#pragma unroll
        for (int j = 0; j < 4; j++) o[nt][j] = 0.f;

    for (int k0 = 0; k0 < 256; k0 += 64) {
        __syncthreads();
#pragma unroll
        for (int it = 0; it < 4; it++) {
            int j = tid + it * 256;
            int rr = j >> 3, c8 = j & 7;
            const float* src = &A[(row0 + rr) * 256 + k0 + c8 * 8];
            *(uint4*)&As[rr * 72 + c8 * 8] =
                pack8h(*(const float4*)src, *(const float4*)(src + 4));
        }
#pragma unroll
        for (int it = 0; it < 2; it++) {
            int j = tid + it * 256;
            int rr = j >> 3, c8 = j & 7;
            const float* src = &W[(k0 + rr) * 512 + col0 + c8 * 8];
            *(uint4*)&Ws[rr * 72 + c8 * 8] =
                pack8h(*(const float4*)src, *(const float4*)(src + 4));
        }
        __syncthreads();
#pragma unroll
        for (int kk = 0; kk < 4; kk++) {
            uint32_t a[4];
            ldm_x4(a, As + arow * 72 + kk * 16 + acoff);
#pragma unroll
            for (int dtp = 0; dtp < 4; dtp++) {
                uint32_t b[4];
                ldm_x4_trans(b, Ws + (kk * 16 + brow) * 72 + dtp * 16 + bcoff);
                mma_f16(o[2 * dtp],     a[0], a[1], a[2], a[3], b[0], b[1]);
                mma_f16(o[2 * dtp + 1], a[0], a[1], a[2], a[3], b[2], b[3]);
            }
        }
    }

    const int r = row0 + wid * 16 + g;
#pragma unroll
    for (int nt = 0; nt < 8; nt++) {
        int c = col0 + nt * 8 + 2 * q;
        float b0 = bias[c], b1 = bias[c + 1];
        __half2 h0 = __floats2half2_rn(o[nt][0] + b0, o[nt][1] + b1);
        __half2 h1 = __floats2half2_rn(o[nt][2] + b0, o[nt][3] + b1);
        *(uint32_t*)&C[r * 512 + c] = *(uint32_t*)&h0;
        *(uint32_t*)&C[(r + 8) * 512 + c] = *(uint32_t*)&h1;
    }
}

// ---------------------------------------------------------------------------
// Score kernel (fp16 mma): S[128n x 128m] = K1h K2h^T, P = exp(S*scale) -> fp16
// + row/col sums. grid (32, 32, 8), 256 thr.
// ---------------------------------------------------------------------------
__global__ __launch_bounds__(256) void score_kernel() {
    extern __shared__ __half smh[];
    __half* As = smh;                          // [128][72]
    __half* Bs = smh + 128 * 72;               // [128][72]
    uint32_t* PsU = (uint32_t*)(smh + 2 * 128 * 72);  // [128][68] fp16x2

    const int head = blockIdx.z;
    const int n0 = blockIdx.y * 128;
    const int m0 = blockIdx.x * 128;
    const int hc = head * 64;
    const int tid = threadIdx.x;
    const int lane = tid & 31;
    const int wid = tid >> 5;
    const int q = lane & 3, g = lane >> 2;
    const int wn = wid >> 1, wm = wid & 1;
    const int rbase = wn * 32;
    const int cbase = wm * 64;

#pragma unroll
    for (int it = 0; it < 4; it++) {
        int j = tid + it * 256;
        int rr = j >> 3, c8 = j & 7;
        cp16(As + rr * 72 + c8 * 8, g_K1H + (n0 + rr) * 512 + hc + c8 * 8);
        cp16(Bs + rr * 72 + c8 * 8, g_K2H + (m0 + rr) * 512 + hc + c8 * 8);
    }
    asm volatile("cp.async.commit_group;" ::: "memory");
    asm volatile("cp.async.wait_group 0;" ::: "memory");
    __syncthreads();

    float cps[8][2];
#pragma unroll
    for (int nt = 0; nt < 8; nt++) { cps[nt][0] = 0.f; cps[nt][1] = 0.f; }

#pragma unroll
    for (int mt = 0; mt < 2; mt++) {
        const int arow_lm = rbase + mt * 16 + (lane & 7) + ((lane >> 3) & 1) * 8;
        const int acoff = (lane >> 4) * 8;
        uint32_t af[4][4];
#pragma unroll
        for (int kk = 0; kk < 4; kk++)
            ldm_x4(af[kk], As + arow_lm * 72 + kk * 16 + acoff);

        const int arow = rbase + mt * 16 + g;
        float rp0 = 0.f, rp1 = 0.f;
#pragma unroll
        for (int nt = 0; nt < 8; nt++) {
            float s[4] = {0.f, 0.f, 0.f, 0.f};
            const int browx = cbase + nt * 8 + g;
#pragma unroll
            for (int kk = 0; kk < 4; kk++) {
                const uint32_t* bp = (const uint32_t*)(Bs + browx * 72 + kk * 16);
                mma_f16(s, af[kk][0], af[kk][1], af[kk][2], af[kk][3], bp[q], bp[q + 4]);
            }
            float p0 = __expf(s[0] * SCALE);
            float p1 = __expf(s[1] * SCALE);
            float p2 = __expf(s[2] * SCALE);
            float p3 = __expf(s[3] * SCALE);
            rp0 += p0 + p1; rp1 += p2 + p3;
            cps[nt][0] += p0 + p2; cps[nt][1] += p1 + p3;
            __half2 h0 = __floats2half2_rn(p0, p1);
            __half2 h1 = __floats2half2_rn(p2, p3);
            int ucol = cbase / 2 + nt * 4 + q;
            PsU[arow * 68 + ucol] = *(uint32_t*)&h0;
            PsU[(arow + 8) * 68 + ucol] = *(uint32_t*)&h1;
        }
        rp0 += __shfl_xor_sync(FULLM, rp0, 1);
        rp0 += __shfl_xor_sync(FULLM, rp0, 2);
        rp1 += __shfl_xor_sync(FULLM, rp1, 1);
        rp1 += __shfl_xor_sync(FULLM, rp1, 2);
        if (q == 0) {
            atomicAdd(&g_rsum[head * Nn + n0 + arow], rp0);
            atomicAdd(&g_rsum[head * Nn + n0 + arow + 8], rp1);
        }
    }

#pragma unroll
    for (int nt = 0; nt < 8; nt++) {
        float v0 = cps[nt][0], v1 = cps[nt][1];
        v0 += __shfl_xor_sync(FULLM, v0, 4);
        v0 += __shfl_xor_sync(FULLM, v0, 8);
        v0 += __shfl_xor_sync(FULLM, v0, 16);
        v1 += __shfl_xor_sync(FULLM, v1, 4);
        v1 += __shfl_xor_sync(FULLM, v1, 8);
        v1 += __shfl_xor_sync(FULLM, v1, 16);
        if (lane < 4) {
            atomicAdd(&g_csum[head * Nn + m0 + cbase + nt * 8 + 2 * q], v0);
            atomicAdd(&g_csum[head * Nn + m0 + cbase + nt * 8 + 2 * q + 1], v1);
        }
    }

    __syncthreads();
    {
        int row = tid >> 1, half = tid & 1;
        __half* dst = g_Ph + ((size_t)(head * Nn + n0 + row)) * Nn + m0;
#pragma unroll
        for (int i = 0; i < 8; i++) {
            uint4 v = *(uint4*)&PsU[row * 68 + (half + 2 * i) * 4];
            *(uint4*)(dst + (half + 2 * i) * 8) = v;
        }
    }
}

// ---------------------------------------------------------------------------
// PV kernel (fp16, k-split x2): grid (32, 8, 4), z = dir*2 + ks.
//   dir=0: o2 partial = P[rows blk0..][ks half] @ V2
//   dir=1: o1 partial = P^T[cols blk0..][ks half] @ V1
// Raw (unnormalized) partial outputs to g_Op[z], fp16.
// ---------------------------------------------------------------------------
#define PV_PSTRIDE 9216   // fp16 elems per P stage (max of 128*72, 64*136)
#define PV_VSTRIDE 4608   // 64*72
#define PV_KT 32          // local k-chunks (of 64) per CTA

__global__ __launch_bounds__(256) void pv_kernel() {
    extern __shared__ __half smp[];
    __half* Pb = smp;
    __half* Vb = smp + 2 * PV_PSTRIDE;

    const int head = blockIdx.y;
    const int blk0 = blockIdx.x * 128;
    const int hc = head * 64;
    const int z = blockIdx.z;
    const int dir = z >> 1;
    const int kb0 = (z & 1) * PV_KT;
    const int tid = threadIdx.x;
    const int lane = tid & 31, wid = tid >> 5;
    const int q = lane & 3, g = lane >> 2;

    const __half* Vg = dir ? g_V1H : g_V2H;

    float o[8][4];
#pragma unroll
    for (int dt = 0; dt < 8; dt++)
#pragma unroll
        for (int j = 0; j < 4; j++) o[dt][j] = 0.f;

    auto issue = [&](int kbl, int buf) {
        const int kb = kb0 + kbl;
        __half* Pd = Pb + buf * PV_PSTRIDE;
        __half* Vd = Vb + buf * PV_VSTRIDE;
        if (dir == 0) {
#pragma unroll
            for (int it = 0; it < 4; it++) {
                int j = tid + it * 256;
                int rr = j >> 3, cc = j & 7;
                cp16(Pd + rr * 72 + cc * 8,
                     g_Ph + ((size_t)(head * Nn + blk0 + rr)) * Nn + kb * 64 + cc * 8);
            }
        } else {
#pragma unroll
            for (int it = 0; it < 4; it++) {
                int j = tid + it * 256;
                int rr = j >> 4, cc = j & 15;
                cp16(Pd + rr * 136 + cc * 8,
                     g_Ph + ((size_t)(head * Nn + kb * 64 + rr)) * Nn + blk0 + cc * 8);
            }
        }
#pragma unroll
        for (int it = 0; it < 2; it++) {
            int j = tid + it * 256;
            int rr = j >> 3, cc = j & 7;
            cp16(Vd + rr * 72 + cc * 8, Vg + (kb * 64 + rr) * 512 + hc + cc * 8);
        }
        asm volatile("cp.async.commit_group;" ::: "memory");
    };

    issue(0, 0);
    issue(1, 1);

    const int brow = ((lane >> 3) & 1) * 8 + (lane & 7);
    const int bcoff = (lane >> 4) * 8;

    for (int kb = 0; kb < PV_KT; kb++) {
        if (kb == PV_KT - 1) asm volatile("cp.async.wait_group 0;" ::: "memory");
        else                 asm volatile("cp.async.wait_group 1;" ::: "memory");
        __syncthreads();

        const __half* Pc = Pb + (kb & 1) * PV_PSTRIDE;
        const __half* Vc = Vb + (kb & 1) * PV_VSTRIDE;

#pragma unroll
        for (int kc = 0; kc < 4; kc++) {
            uint32_t a[4];
            if (dir == 0) {
                int arow = wid * 16 + (lane & 7) + ((lane >> 3) & 1) * 8;
                int acol = kc * 16 + (lane >> 4) * 8;
                ldm_x4(a, Pc + arow * 72 + acol);
            } else {
                int krow = kc * 16 + (lane & 7) + ((lane >> 4) & 1) * 8;
                int mcol = wid * 16 + ((lane >> 3) & 1) * 8;
                ldm_x4_trans(a, Pc + krow * 136 + mcol);
            }
#pragma unroll
            for (int dtp = 0; dtp < 4; dtp++) {
                uint32_t b[4];
                ldm_x4_trans(b, Vc + (kc * 16 + brow) * 72 + dtp * 16 + bcoff);
                mma_f16(o[2 * dtp],     a[0], a[1], a[2], a[3], b[0], b[1]);
                mma_f16(o[2 * dtp + 1], a[0], a[1], a[2], a[3], b[2], b[3]);
            }
        }
        __syncthreads();
        if (kb + 2 < PV_KT) issue(kb + 2, kb & 1);
    }

    const int rA = blk0 + wid * 16 + g;
    __half* Og = g_Op[z] + (size_t)rA * 512 + hc;
#pragma unroll
    for (int dt = 0; dt < 8; dt++) {
        __half2 h0 = __floats2half2_rn(o[dt][0], o[dt][1]);
        __half2 h1 = __floats2half2_rn(o[dt][2], o[dt][3]);
        *(uint32_t*)&Og[dt * 8 + 2 * q] = *(uint32_t*)&h0;
        *(uint32_t*)&Og[8 * 512 + dt * 8 + 2 * q] = *(uint32_t*)&h1;
    }
}

// ---------------------------------------------------------------------------
// Output GEMM (fp16 mma): out[4096,256] = ((Oa+Ob)*inv) @ Wo + bias
// grid (4, 32, 2): z=0 -> o1 (parts 2,3, csum-inv, wo1), z=1 -> o2 (parts 0,1)
// ---------------------------------------------------------------------------
__global__ __launch_bounds__(256) void outproj_f16_kernel(Ptrs in, float* out) {
    const __half *P0, *P1;
    const float *inv, *W, *bias;
    float* C;
    if (blockIdx.z == 0) {
        P0 = g_Op[2]; P1 = g_Op[3]; inv = g_csum;
        W = in.p[12]; bias = in.p[13]; C = out;
    } else {
        P0 = g_Op[0]; P1 = g_Op[1]; inv = g_rsum;
        W = in.p[14]; bias = in.p[15]; C = out + Nn * 256;
    }
    __shared__ __half As[128 * 72];
    __shared__ __half Ws[64 * 72];

    const int tid = threadIdx.x;
    const int lane = tid & 31, wid = tid >> 5;
    const int q = lane & 3, g = lane >> 2;
    const int row0 = blockIdx.y * 128;
    const int col0 = blockIdx.x * 64;
    const int brow = ((lane >> 3) & 1) * 8 + (lane & 7);
    const int bcoff = (lane >> 4) * 8;
    const int arow = wid * 16 + (lane & 7) + ((lane >> 3) & 1) * 8;
    const int acoff = (lane >> 4) * 8;

    float o[8][4];
#pragma unroll
    for (int nt = 0; nt < 8; nt++)
#pragma unroll
        for (int j = 0; j < 4; j++) o[nt][j] = 0.f;

    for (int k0 = 0; k0 < 512; k0 += 64) {
        const int head = k0 >> 6;
        __syncthreads();
        // A staging: combine partials + normalize -> fp16
#pragma unroll
        for (int it = 0; it < 4; it++) {
            int j = tid + it * 256;
            int rr = j >> 3, c8 = j & 7;
            size_t idx = (size_t)(row0 + rr) * 512 + k0 + c8 * 8;
            uint4 u0 = *(const uint4*)(P0 + idx);
            uint4 u1 = *(const uint4*)(P1 + idx);
            float iv = inv[head * Nn + row0 + rr];
            const __half2* h0 = (const __half2*)&u0;
            const __half2* h1 = (const __half2*)&u1;
            uint4 uo;
            __half2* ho = (__half2*)&uo;
#pragma unroll
            for (int e = 0; e < 4; e++) {
                float2 f0 = __half22float2(h0[e]);
                float2 f1 = __half22float2(h1[e]);
                ho[e] = __floats2half2_rn((f0.x + f1.x) * iv, (f0.y + f1.y) * iv);
            }
            *(uint4*)&As[rr * 72 + c8 * 8] = uo;
        }
#pragma unroll
        for (int it = 0; it < 2; it++) {
            int j = tid + it * 256;
            int rr = j >> 3, c8 = j & 7;
            const float* src = &W[(k0 + rr) * 256 + col0 + c8 * 8];
            *(uint4*)&Ws[rr * 72 + c8 * 8] =
                pack8h(*(const float4*)src, *(const float4*)(src + 4));
        }
        __syncthreads();
#pragma unroll
        for (int kk = 0; kk < 4; kk++) {
            uint32_t a[4];
            ldm_x4(a, As + arow * 72 + kk * 16 + acoff);
#pragma unroll
            for (int dtp = 0; dtp < 4; dtp++) {
                uint32_t b[4];
                ldm_x4_trans(b, Ws + (kk * 16 + brow) * 72 + dtp * 16 + bcoff);
                mma_f16(o[2 * dtp],     a[0], a[1], a[2], a[3], b[0], b[1]);
                mma_f16(o[2 * dtp + 1], a[0], a[1], a[2], a[3], b[2], b[3]);
            }
        }
    }

    const int r = row0 + wid * 16 + g;
#pragma unroll
    for (int nt = 0; nt < 8; nt++) {
        int c = col0 + nt * 8 + 2 * q;
        float b0 = bias[c], b1 = bias[c + 1];
        *(float2*)&C[r * 256 + c] = make_float2(o[nt][0] + b0, o[nt][1] + b1);
        *(float2*)&C[(r + 8) * 256 + c] = make_float2(o[nt][2] + b0, o[nt][3] + b1);
    }
}

extern "C" void kernel_launch(void* const* d_in, const int* in_sizes, int n_in,
                              void* d_out, int out_size) {
    Ptrs ptrs;
    for (int i = 0; i < 16; i++) ptrs.p[i] = (const float*)d_in[i];
    float* out = (float*)d_out;

    cudaFuncSetAttribute(score_kernel, cudaFuncAttributeMaxDynamicSharedMemorySize,
                         2 * 128 * 72 * 2 + 128 * 68 * 4);
    cudaFuncSetAttribute(pv_kernel, cudaFuncAttributeMaxDynamicSharedMemorySize,
                         (2 * PV_PSTRIDE + 2 * PV_VSTRIDE) * 2);

    zero_kernel<<<32, 256>>>();
    {
        dim3 grid(512 / 64, Nn / 128, 4);
        proj_f16_kernel<<<grid, 256>>>(ptrs);
    }
    {
        dim3 grid(Nn / 128, Nn / 128, NHEADS);
        score_kernel<<<grid, 256, 2 * 128 * 72 * 2 + 128 * 68 * 4>>>();
    }
    recip_kernel<<<128, 256>>>();
    {
        dim3 grid(Nn / 128, NHEADS, 4);
        pv_kernel<<<grid, 256, (2 * PV_PSTRIDE + 2 * PV_VSTRIDE) * 2>>>();
    }
    {
        dim3 grid(256 / 64, Nn / 128, 2);   // FIXED: 128-row tiles
        outproj_f16_kernel<<<grid, 256>>>(ptrs, out);
    }
}